// round 8
// baseline (speedup 1.0000x reference)
#include <cuda_runtime.h>
#include <float.h>

#define N_NODES 588
#define K_DEG   32
#define NBLK    148
#define NTHR    256
#define NWARPS  8
#define GWARPS  (NBLK*NWARPS)   // 1184

// -------- global scratch (allocation-free: __device__ arrays) --------
__device__ __align__(16) float g_x1[N_NODES * 3];
__device__ __align__(16) float g_act3[256];
__device__ __align__(16) float g_act4[512];
__device__ __align__(16) float g_act5[1024];
__device__ unsigned g_bar_cnt = 0;
__device__ volatile unsigned g_bar_gen = 0;

__device__ __forceinline__ float lrelu(float x) { return x > 0.f ? x : 0.01f * x; }

// Generation-counting grid barrier, self-resetting across graph replays.
// 148 blocks x 256 thr at 1 block/SM: fully co-resident (proven R1/R3).
__device__ __forceinline__ void grid_bar() {
    __threadfence();                           // release prior global writes
    __syncthreads();
    if (threadIdx.x == 0) {
        unsigned gen = g_bar_gen;
        if (atomicAdd(&g_bar_cnt, 1u) == NBLK - 1) {
            g_bar_cnt = 0;
            __threadfence();
            g_bar_gen = gen + 1;
        } else {
            while (g_bar_gen == gen) { }
        }
    }
    __syncthreads();
    __threadfence();                           // acquire
}

__device__ __forceinline__ float warp_sum(float v) {
#pragma unroll
    for (int o = 16; o; o >>= 1) v += __shfl_xor_sync(0xffffffffu, v, o);
    return v;
}

__global__ void __launch_bounds__(NTHR, 1) fused_all(
    const float* __restrict__ features, const int* __restrict__ src,
    const float* __restrict__ t1w, const float* __restrict__ t1b,
    const float* __restrict__ p1w, const float* __restrict__ p1b,
    const float* __restrict__ t2w, const float* __restrict__ t2b,
    const float* __restrict__ p2w, const float* __restrict__ p2b,
    const float* __restrict__ fc1w, const float* __restrict__ fc1b,
    const float* __restrict__ fc2w, const float* __restrict__ fc2b,
    const float* __restrict__ fc3w, const float* __restrict__ fc3b,
    const float* __restrict__ fc4w, const float* __restrict__ fc4b,
    const float* __restrict__ fc5w, const float* __restrict__ fc5b,
    const float* __restrict__ fc6w, const float* __restrict__ fc6b,
    float* __restrict__ out)
{
    const int tid  = threadIdx.x;
    const int bid  = blockIdx.x;
    const int warp = tid >> 5;
    const int lane = tid & 31;
    const int gw   = bid * NWARPS + warp;      // 0..1183

    // ======== weight preloads into registers: issued before any barrier ========
    // fc3 row for blocks 0..31 (8 rows per block, warp-per-row)
    float4 w3 = make_float4(0.f, 0.f, 0.f, 0.f);
    float  b3 = 0.f;
    if (bid < 32) {
        int k3 = bid * 8 + warp;
        w3 = *((const float4*)(fc3w + k3 * 128) + lane);
        b3 = fc3b[k3];
    }
    // fc4 row gw (<512)
    float4 W4[2]; float b4 = 0.f;
    if (gw < 512) {
        const float4* p = (const float4*)(fc4w + gw * 256);
#pragma unroll
        for (int it = 0; it < 2; it++) W4[it] = p[lane + 32 * it];
        b4 = fc4b[gw];
    }
    // fc5 row gw (<1024)
    float4 W5[4]; float b5 = 0.f;
    if (gw < 1024) {
        const float4* p = (const float4*)(fc5w + gw * 512);
#pragma unroll
        for (int it = 0; it < 4; it++) W5[it] = p[lane + 32 * it];
        b5 = fc5b[gw];
    }
    // fc6 row gw (always < 1764)
    float4 W6[8]; float b6;
    {
        const float4* p = (const float4*)(fc6w + (size_t)gw * 1024);
#pragma unroll
        for (int it = 0; it < 8; it++) W6[it] = p[lane + 32 * it];
        b6 = fc6b[gw];
    }

    __shared__ float a1[N_NODES * 3], c1[N_NODES * 3];   // phase A (reused as scratch)
    __shared__ float a2[N_NODES], c2[N_NODES], x2[N_NODES];
    __shared__ float y10[10];
    __shared__ __align__(16) float y128[128];

    // ================= Phase A: EC1 on blocks 0..2 (196 nodes each) =================
    // msg = a1[src] + c1[dst]; max over src commutes with +c1.
    if (bid < 3) {
        float T1[9], P1[9], B1[3];
#pragma unroll
        for (int i = 0; i < 9; i++) { T1[i] = t1w[i]; P1[i] = p1w[i]; }
#pragma unroll
        for (int i = 0; i < 3; i++) B1[i] = t1b[i] + p1b[i];

        for (int j = tid; j < N_NODES; j += NTHR) {
            float v0 = features[j * 3], v1 = features[j * 3 + 1], v2 = features[j * 3 + 2];
#pragma unroll
            for (int k = 0; k < 3; k++) {
                float av = T1[k * 3] * v0 + T1[k * 3 + 1] * v1 + T1[k * 3 + 2] * v2;
                float pv = P1[k * 3] * v0 + P1[k * 3 + 1] * v1 + P1[k * 3 + 2] * v2;
                a1[j * 3 + k] = av;
                c1[j * 3 + k] = B1[k] + pv - av;
            }
        }
        __syncthreads();

        int i = bid * 196 + tid;                // 3*196 = 588
        if (tid < 196) {
            float m0 = -FLT_MAX, m1 = -FLT_MAX, m2 = -FLT_MAX;
            const int* sp = src + i * K_DEG;
#pragma unroll
            for (int e = 0; e < K_DEG; e++) {
                int s = sp[e] * 3;
                m0 = fmaxf(m0, a1[s]);
                m1 = fmaxf(m1, a1[s + 1]);
                m2 = fmaxf(m2, a1[s + 2]);
            }
            g_x1[i * 3]     = m0 + c1[i * 3];
            g_x1[i * 3 + 1] = m1 + c1[i * 3 + 1];
            g_x1[i * 3 + 2] = m2 + c1[i * 3 + 2];
        }
    }
    grid_bar();   // BAR1: g_x1 ready

    // ====== Phase B: blocks 0..31 — EC2 + fc1 + fc2 (redundant) + fc3 (8 rows) ======
    if (bid < 32) {
        float T2[3], P2[3];
#pragma unroll
        for (int i = 0; i < 3; i++) { T2[i] = t2w[i]; P2[i] = p2w[i]; }
        float B2 = t2b[0] + p2b[0];
        for (int j = tid; j < N_NODES; j += NTHR) {
            float v0 = g_x1[j * 3], v1 = g_x1[j * 3 + 1], v2 = g_x1[j * 3 + 2];
            float av = T2[0] * v0 + T2[1] * v1 + T2[2] * v2;
            a2[j] = av;
            c2[j] = B2 + P2[0] * v0 + P2[1] * v1 + P2[2] * v2 - av;
        }
        __syncthreads();

        for (int i = tid; i < N_NODES; i += NTHR) {
            float m = -FLT_MAX;
            const int* sp = src + i * K_DEG;
#pragma unroll
            for (int e = 0; e < K_DEG; e++) m = fmaxf(m, a2[sp[e]]);
            x2[i] = m + c2[i];
        }
        __syncthreads();

        // fc1: [588]->[10], warp-per-output; 588 = 18*32 + 12
        for (int k = warp; k < 10; k += 8) {
            const float* wrow = fc1w + k * N_NODES;
            float acc = 0.f;
#pragma unroll
            for (int it = 0; it < 18; it++) {
                int j = it * 32 + lane;
                acc += x2[j] * wrow[j];
            }
            if (lane < 12) {
                int j = 18 * 32 + lane;
                acc += x2[j] * wrow[j];
            }
            acc = warp_sum(acc);
            if (lane == 0) y10[k] = lrelu(acc + fc1b[k]);
        }
        __syncthreads();

        // fc2: [10]->[128]
        if (tid < 128) {
            float acc = fc2b[tid];
#pragma unroll
            for (int j = 0; j < 10; j++) acc += y10[j] * fc2w[tid * 10 + j];
            y128[tid] = lrelu(acc);
        }
        __syncthreads();

        // fc3: this block's 8 rows, warp-per-row, preloaded w3
        {
            int k3 = bid * 8 + warp;
            float4 a4 = ((const float4*)y128)[lane];
            float acc = w3.x * a4.x + w3.y * a4.y + w3.z * a4.z + w3.w * a4.w;
            acc = warp_sum(acc);
            if (lane == 0) g_act3[k3] = lrelu(acc + b3);
        }
    }
    grid_bar();   // BAR2: g_act3 ready

    // ================= Phase C: fc4 [256]->[512], warp-per-row =================
    if (gw < 512) {
        const float4* ar = (const float4*)g_act3;
        float acc = 0.f;
#pragma unroll
        for (int it = 0; it < 2; it++) {
            float4 a4 = ar[lane + 32 * it];
            acc += W4[it].x * a4.x + W4[it].y * a4.y + W4[it].z * a4.z + W4[it].w * a4.w;
        }
        acc = warp_sum(acc);
        if (lane == 0) g_act4[gw] = lrelu(acc + b4);
    }
    grid_bar();   // BAR3: g_act4 ready

    // ================= Phase D: fc5 [512]->[1024], warp-per-row =================
    if (gw < 1024) {
        const float4* ar = (const float4*)g_act4;
        float acc = 0.f;
#pragma unroll
        for (int it = 0; it < 4; it++) {
            float4 a4 = ar[lane + 32 * it];
            acc += W5[it].x * a4.x + W5[it].y * a4.y + W5[it].z * a4.z + W5[it].w * a4.w;
        }
        acc = warp_sum(acc);
        if (lane == 0) g_act5[gw] = lrelu(acc + b5);
    }
    grid_bar();   // BAR4: g_act5 ready

    // ================= Phase E: fc6 [1024]->[1764] =================
    {
        int k1 = gw + GWARPS;                  // second row, valid iff < 1764
        bool two = (k1 < 1764);
        int k1c = two ? k1 : 0;

        const float4* ar = (const float4*)g_act5;
        float4 A[8];
#pragma unroll
        for (int it = 0; it < 8; it++) A[it] = ar[lane + 32 * it];

        // front-batch second-row weight loads with the activation loads
        const float4* w1 = (const float4*)(fc6w + (size_t)k1c * 1024);
        float4 WB[8];
#pragma unroll
        for (int it = 0; it < 8; it++) WB[it] = w1[lane + 32 * it];

        float acc0 = 0.f, acc1 = 0.f;
#pragma unroll
        for (int it = 0; it < 8; it++) {
            acc0 += W6[it].x * A[it].x + W6[it].y * A[it].y + W6[it].z * A[it].z + W6[it].w * A[it].w;
            acc1 += WB[it].x * A[it].x + WB[it].y * A[it].y + WB[it].z * A[it].z + WB[it].w * A[it].w;
        }
        acc0 = warp_sum(acc0);
        acc1 = warp_sum(acc1);
        if (lane == 0) {
            out[gw] = acc0 + b6;
            if (two) out[k1] = acc1 + fc6b[k1];
        }
    }
}

extern "C" void kernel_launch(void* const* d_in, const int* in_sizes, int n_in,
                              void* d_out, int out_size) {
    // metadata order:
    // 0 features, 1 src, 2 dst (unused: dst[e] == e/32 by construction),
    // 3 theta1_w, 4 theta1_b, 5 phi1_w, 6 phi1_b,
    // 7 theta2_w, 8 theta2_b, 9 phi2_w, 10 phi2_b,
    // 11 fc1_w, 12 fc1_b, 13 fc2_w, 14 fc2_b, 15 fc3_w, 16 fc3_b,
    // 17 fc4_w, 18 fc4_b, 19 fc5_w, 20 fc5_b, 21 fc6_w, 22 fc6_b
    fused_all<<<NBLK, NTHR>>>(
        (const float*)d_in[0], (const int*)d_in[1],
        (const float*)d_in[3], (const float*)d_in[4],
        (const float*)d_in[5], (const float*)d_in[6],
        (const float*)d_in[7], (const float*)d_in[8],
        (const float*)d_in[9], (const float*)d_in[10],
        (const float*)d_in[11], (const float*)d_in[12],
        (const float*)d_in[13], (const float*)d_in[14],
        (const float*)d_in[15], (const float*)d_in[16],
        (const float*)d_in[17], (const float*)d_in[18],
        (const float*)d_in[19], (const float*)d_in[20],
        (const float*)d_in[21], (const float*)d_in[22],
        (float*)d_out);
}